// round 2
// baseline (speedup 1.0000x reference)
#include <cuda_runtime.h>
#include <math.h>

// ---------------- shapes (fixed by the problem) ----------------
#define BERT 768
#define CTRY 24
#define CODE 8
#define GAZ  9
#define MIX  24
#define NFEAT 13
#define CMAX 64
#define B_MAX 2048
#define NCTRY_MAX 512
#define NCODES_MAX 1024

// ---------------- device scratch (no allocation allowed) ----------------
__device__ float g_cet [NCTRY_MAX * CTRY];   // projected country embeddings
__device__ float g_cetn[NCTRY_MAX];          // their norms
__device__ float g_coden[NCODES_MAX];        // code-embedding norms
__device__ float g_proj[B_MAX * 80];         // per-row: x(24) | x_code(8) | x_other(24) | x_doc(24)

// =====================================================================
// Kernel A: cet[i] = country_emb[i] @ W_cet.T + b_cet  (+ row norm)
// grid = nCtry, block = 128 (4 warps, 6 outs each)
// =====================================================================
__global__ void k_cet(const float* __restrict__ cemb,
                      const float* __restrict__ Wcet,
                      const float* __restrict__ bcet)
{
    int i = blockIdx.x;
    int warp = threadIdx.x >> 5, lane = threadIdx.x & 31;
    __shared__ float sv[CTRY];
    const float* e = cemb + (size_t)i * BERT;

    #pragma unroll
    for (int t = 0; t < 6; t++) {
        int j = warp * 6 + t;
        const float* w = Wcet + (size_t)j * BERT;
        float a = 0.f;
        for (int k = lane * 4; k < BERT; k += 128) {
            float4 ev = *(const float4*)(e + k);
            float4 wv = *(const float4*)(w + k);
            a += ev.x * wv.x + ev.y * wv.y + ev.z * wv.z + ev.w * wv.w;
        }
        #pragma unroll
        for (int o = 16; o; o >>= 1) a += __shfl_xor_sync(0xffffffffu, a, o);
        if (lane == 0) sv[j] = a + bcet[j];
    }
    __syncthreads();
    if (threadIdx.x < 32) {
        float v = (lane < CTRY) ? sv[lane] : 0.f;
        if (lane < CTRY) g_cet[i * CTRY + lane] = v;
        float s = v * v;
        #pragma unroll
        for (int o = 16; o; o >>= 1) s += __shfl_xor_sync(0xffffffffu, s, o);
        if (lane == 0) g_cetn[i] = sqrtf(s);
    }
}

// =====================================================================
// Kernel A2: norms of the 8-dim code embeddings
// =====================================================================
__global__ void k_coden(const float* __restrict__ codeTab, int n)
{
    int i = blockIdx.x * blockDim.x + threadIdx.x;
    if (i < n) {
        float s = 0.f;
        #pragma unroll
        for (int j = 0; j < CODE; j++) { float v = codeTab[i * CODE + j]; s += v * v; }
        g_coden[i] = sqrtf(s);
    }
}

// =====================================================================
// Kernel B: projections. One block = 16 batch rows, 256 threads.
// lane[0..15] -> row, lane bit4 -> k-half; warp w owns k slice [s*48, s*48+48)
// with s = warp*2 + half. W loads broadcast across the 16 row-lanes.
// 10 batches of 8 outputs; cross-slice reduction through smem.
// out layout: 0-23 x(t2c) | 24-31 x_code | 32-55 x_other(ctx) | 56-79 x_doc(ctx)
// =====================================================================
__global__ void __launch_bounds__(256, 2) k_proj(
    const float* __restrict__ place, const float* __restrict__ other,
    const float* __restrict__ doc,
    const float* __restrict__ Wt2c, const float* __restrict__ bt2c,
    const float* __restrict__ Wcode, const float* __restrict__ bcode,
    const float* __restrict__ Wctx, const float* __restrict__ bctx,
    int Bn)
{
    __shared__ float sred[8 * 136];          // [warp][row*8 + ob], padded stride
    const int tid  = threadIdx.x;
    const int warp = tid >> 5, lane = tid & 31;
    const int r    = lane & 15, half = lane >> 4;
    const int s    = (warp << 1) | half;     // k-slice id 0..15
    const int row0 = blockIdx.x * 16;
    const int row  = min(row0 + r, Bn - 1);

    const float* srcs[3] = { place, other, doc };
    float xreg[48];

    #pragma unroll 1
    for (int bb = 0; bb < 10; bb++) {
        int src_id = (bb < 4) ? 0 : ((bb < 7) ? 1 : 2);
        if (bb == 0 || bb == 4 || bb == 7) {
            const float* xp = srcs[src_id] + (size_t)row * BERT + s * 48;
            #pragma unroll
            for (int j = 0; j < 12; j++) {
                float4 v = __ldg((const float4*)(xp + j * 4));
                xreg[j * 4 + 0] = v.x; xreg[j * 4 + 1] = v.y;
                xreg[j * 4 + 2] = v.z; xreg[j * 4 + 3] = v.w;
            }
        }
        const float* Wb; const float* biasb; int wr0;
        if      (bb < 3)  { Wb = Wt2c;  biasb = bt2c;  wr0 = bb * 8; }
        else if (bb == 3) { Wb = Wcode; biasb = bcode; wr0 = 0; }
        else if (bb < 7)  { Wb = Wctx;  biasb = bctx;  wr0 = (bb - 4) * 8; }
        else              { Wb = Wctx;  biasb = bctx;  wr0 = (bb - 7) * 8; }

        float acc[8];
        #pragma unroll
        for (int ob = 0; ob < 8; ob++) {
            const float* w = Wb + (size_t)(wr0 + ob) * BERT + s * 48;
            float a = 0.f;
            #pragma unroll
            for (int j = 0; j < 12; j++) {
                float4 wv = __ldg((const float4*)(w + j * 4));
                a += xreg[j * 4 + 0] * wv.x + xreg[j * 4 + 1] * wv.y
                   + xreg[j * 4 + 2] * wv.z + xreg[j * 4 + 3] * wv.w;
            }
            acc[ob] = a;
        }
        // fold the two k-halves within the warp
        #pragma unroll
        for (int ob = 0; ob < 8; ob++)
            acc[ob] += __shfl_xor_sync(0xffffffffu, acc[ob], 16);
        if (half == 0) {
            float* p = sred + warp * 136 + r * 8;
            #pragma unroll
            for (int ob = 0; ob < 8; ob++) p[ob] = acc[ob];
        }
        __syncthreads();
        if (tid < 128) {
            int rr = tid >> 3, ob = tid & 7;
            float a = 0.f;
            #pragma unroll
            for (int w2 = 0; w2 < 8; w2++) a += sred[w2 * 136 + rr * 8 + ob];
            if (row0 + rr < Bn)
                g_proj[(row0 + rr) * 80 + bb * 8 + ob] = a + biasb[wr0 + ob];
        }
        __syncthreads();
    }
}

// =====================================================================
// Kernel C: gather + 4 cosine sims + MLP(13->24->24->1) + softmax over C=64.
// Block = 256 threads = 4 batch rows x 64 candidates.
// =====================================================================
__global__ void __launch_bounds__(256) k_mlp(
    const int* __restrict__ fcodes, const int* __restrict__ ccodes,
    const float* __restrict__ gaz,  const float* __restrict__ codeTab,
    const float* __restrict__ W1, const float* __restrict__ b1,
    const float* __restrict__ W2, const float* __restrict__ b2,
    const float* __restrict__ WL, const float* __restrict__ bL,
    float* __restrict__ out, int Bn)
{
    __shared__ __align__(16) float sW1[MIX * 16];   // 13 padded to 16
    __shared__ __align__(16) float sW2[MIX * MIX];
    __shared__ float sWL[MIX], sB1[MIX], sB2[MIX];
    __shared__ float sX[4 * 80];
    __shared__ float sN[4][4];
    __shared__ float sRed[4][2];
    __shared__ float sbL;

    const int tid = threadIdx.x;
    const int b0  = blockIdx.x * 4;

    for (int i = tid; i < MIX * 16; i += 256) {
        int j = i >> 4, q = i & 15;
        sW1[i] = (q < NFEAT) ? W1[j * NFEAT + q] : 0.f;
    }
    for (int i = tid; i < MIX * MIX; i += 256) sW2[i] = W2[i];
    if (tid < MIX) { sWL[tid] = WL[tid]; sB1[tid] = b1[tid]; sB2[tid] = b2[tid]; }
    if (tid == 0) sbL = bL[0];
    for (int i = tid; i < 4 * 80; i += 256) {
        int bb = min(b0 + i / 80, Bn - 1);
        sX[i] = g_proj[bb * 80 + (i % 80)];
    }
    __syncthreads();

    if (tid < 16) {
        int gg = tid >> 2, which = tid & 3;
        int off = (which == 0) ? 0 : (which == 1) ? 24 : (which == 2) ? 32 : 56;
        int cnt = (which == 1) ? CODE : CTRY;
        float ss = 0.f;
        for (int j = 0; j < cnt; j++) { float v = sX[gg * 80 + off + j]; ss += v * v; }
        sN[gg][which] = fmaxf(sqrtf(ss), 1e-8f);
    }
    __syncthreads();

    const int g = tid >> 6;          // row within block
    const int c = tid & 63;
    const int b = min(b0 + g, Bn - 1);
    const int idx = b * CMAX + c;
    const int fc = fcodes[idx], cc = ccodes[idx];
    const float* sx = sX + g * 80;

    // sims against projected country embedding (shared 24-float gather)
    const float* cet = g_cet + cc * CTRY;
    float d1 = 0.f, d3 = 0.f, d4 = 0.f;
    #pragma unroll
    for (int j = 0; j < CTRY; j++) {
        float cv = __ldg(cet + j);
        d1 += sx[j]      * cv;
        d3 += sx[32 + j] * cv;
        d4 += sx[56 + j] * cv;
    }
    float nb = fmaxf(g_cetn[cc], 1e-8f);

    float feat[16];
    feat[0] = d1 / (sN[g][0] * nb);
    feat[2] = d3 / (sN[g][2] * nb);
    feat[3] = d4 / (sN[g][3] * nb);

    const float* fe = codeTab + fc * CODE;
    float d2 = 0.f;
    #pragma unroll
    for (int j = 0; j < CODE; j++) d2 += sx[24 + j] * __ldg(fe + j);
    feat[1] = d2 / (sN[g][1] * fmaxf(g_coden[fc], 1e-8f));

    #pragma unroll
    for (int j = 0; j < GAZ; j++) feat[4 + j] = __ldg(gaz + (size_t)idx * GAZ + j);
    feat[13] = feat[14] = feat[15] = 0.f;

    float h1[MIX];
    #pragma unroll
    for (int j = 0; j < MIX; j++) {
        float a = sB1[j];
        #pragma unroll
        for (int q = 0; q < 4; q++) {
            float4 w = ((const float4*)sW1)[j * 4 + q];
            a += w.x * feat[q * 4 + 0] + w.y * feat[q * 4 + 1]
               + w.z * feat[q * 4 + 2] + w.w * feat[q * 4 + 3];
        }
        h1[j] = 1.f / (1.f + __expf(-a));
    }
    float h2[MIX];
    #pragma unroll
    for (int j = 0; j < MIX; j++) {
        float a = sB2[j];
        #pragma unroll
        for (int q = 0; q < 6; q++) {
            float4 w = ((const float4*)sW2)[j * 6 + q];
            a += w.x * h1[q * 4 + 0] + w.y * h1[q * 4 + 1]
               + w.z * h1[q * 4 + 2] + w.w * h1[q * 4 + 3];
        }
        h2[j] = 1.f / (1.f + __expf(-a));
    }
    float last = sbL;
    #pragma unroll
    for (int q = 0; q < MIX; q++) last += sWL[q] * h2[q];

    // softmax over the 64 candidates (2 warps per group)
    float m = last;
    #pragma unroll
    for (int o = 16; o; o >>= 1) m = fmaxf(m, __shfl_xor_sync(0xffffffffu, m, o));
    int wh = (tid >> 5) & 1;
    if ((tid & 31) == 0) sRed[g][wh] = m;
    __syncthreads();
    m = fmaxf(sRed[g][0], sRed[g][1]);
    float e = __expf(last - m);
    float ss = e;
    #pragma unroll
    for (int o = 16; o; o >>= 1) ss += __shfl_xor_sync(0xffffffffu, ss, o);
    __syncthreads();
    if ((tid & 31) == 0) sRed[g][wh] = ss;
    __syncthreads();
    ss = sRed[g][0] + sRed[g][1];
    if (b0 + g < Bn) out[idx] = e / ss;
}

// =====================================================================
extern "C" void kernel_launch(void* const* d_in, const int* in_sizes, int n_in,
                              void* d_out, int out_size)
{
    const float* place  = (const float*)d_in[0];
    const float* other  = (const float*)d_in[1];
    const float* doc    = (const float*)d_in[2];
    const int*   fcodes = (const int*)  d_in[3];
    const int*   ccodes = (const int*)  d_in[4];
    const float* gaz    = (const float*)d_in[5];
    const float* codeTab= (const float*)d_in[6];
    const float* ctryTab= (const float*)d_in[7];
    const float* Wcet   = (const float*)d_in[8];
    const float* bcet   = (const float*)d_in[9];
    const float* Wt2c   = (const float*)d_in[10];
    const float* bt2c   = (const float*)d_in[11];
    const float* Wctx   = (const float*)d_in[12];
    const float* bctx   = (const float*)d_in[13];
    const float* Wcode  = (const float*)d_in[14];
    const float* bcode  = (const float*)d_in[15];
    const float* W1     = (const float*)d_in[16];
    const float* b1     = (const float*)d_in[17];
    const float* W2     = (const float*)d_in[18];
    const float* b2     = (const float*)d_in[19];
    const float* WL     = (const float*)d_in[20];
    const float* bL     = (const float*)d_in[21];
    float* out = (float*)d_out;

    int B      = in_sizes[0] / BERT;
    int nCtry  = in_sizes[7] / BERT;
    int nCodes = in_sizes[6] / CODE;

    k_cet  <<<nCtry, 128>>>(ctryTab, Wcet, bcet);
    k_coden<<<(nCodes + 255) / 256, 256>>>(codeTab, nCodes);
    k_proj <<<(B + 15) / 16, 256>>>(place, other, doc,
                                    Wt2c, bt2c, Wcode, bcode, Wctx, bctx, B);
    k_mlp  <<<(B + 3) / 4, 256>>>(fcodes, ccodes, gaz, codeTab,
                                  W1, b1, W2, b2, WL, bL, out, B);
}

// round 3
// speedup vs baseline: 1.2434x; 1.2434x over previous
#include <cuda_runtime.h>
#include <math.h>

typedef unsigned long long u64;

// ---------------- shapes ----------------
#define BERT 768
#define CTRY 24
#define CODE 8
#define GAZ  9
#define MIX  24
#define NFEAT 13
#define CMAX 64
#define B_MAX 2048
#define NCTRY_MAX 512
#define NCODES_MAX 1024

// ---------------- device scratch ----------------
__device__ float g_cet [NCTRY_MAX * CTRY];
__device__ float g_cetn[NCTRY_MAX];
__device__ float g_coden[NCODES_MAX];
__device__ float g_proj[B_MAX * 80];   // x(24) | x_code(8) | x_other(24) | x_doc(24)

// ---------------- f32x2 helpers (sm_10x packed fp32) ----------------
__device__ __forceinline__ void ffma2(u64& d, u64 a, u64 b) {
    asm("fma.rn.f32x2 %0, %1, %2, %0;" : "+l"(d) : "l"(a), "l"(b));
}
__device__ __forceinline__ u64 pack2(float lo, float hi) {
    u64 r; asm("mov.b64 %0, {%1,%2};" : "=l"(r) : "f"(lo), "f"(hi)); return r;
}
__device__ __forceinline__ void unpack2(u64 v, float& lo, float& hi) {
    asm("mov.b64 {%0,%1}, %2;" : "=f"(lo), "=f"(hi) : "l"(v));
}
__device__ __forceinline__ float hsum2(u64 v) {
    float lo, hi; unpack2(v, lo, hi); return lo + hi;
}
__device__ __forceinline__ float sigf(float x) {
    return 1.f / (1.f + __expf(-x));
}

// =====================================================================
// Fused pre-kernel: [0,PB) proj blocks | [PB,PB+nCtry) cet | rest coden
// =====================================================================
__global__ void __launch_bounds__(256, 2) k_pre(
    const float* __restrict__ place, const float* __restrict__ other,
    const float* __restrict__ doc,
    const float* __restrict__ Wt2c, const float* __restrict__ bt2c,
    const float* __restrict__ Wcode, const float* __restrict__ bcode,
    const float* __restrict__ Wctx, const float* __restrict__ bctx,
    const float* __restrict__ cemb, const float* __restrict__ Wcet,
    const float* __restrict__ bcet, const float* __restrict__ codeTab,
    int PB, int nCtry, int nCodes, int Bn)
{
    __shared__ float sred[8 * 129 + 136];
    const int bid  = blockIdx.x;
    const int tid  = threadIdx.x;
    const int warp = tid >> 5, lane = tid & 31;

    if (bid < PB) {
        // ---------- projections: 16 rows, 2 rows/thread, 32 k-slices x 24 ----------
        const int rg   = lane & 7;               // row-pair group
        const int ks   = (warp << 2) | (lane >> 3);  // k-slice 0..31
        const int koff = ks * 24;
        const int row0 = bid * 16;
        const int rA = min(row0 + rg * 2,     Bn - 1);
        const int rB = min(row0 + rg * 2 + 1, Bn - 1);

        u64 xA[12], xB[12];

        #pragma unroll 1
        for (int bb = 0; bb < 10; bb++) {
            if (bb == 0 || bb == 4 || bb == 7) {
                const float* srcp = (bb == 0) ? place : (bb == 4) ? other : doc;
                const ulonglong2* pa = (const ulonglong2*)(srcp + (size_t)rA * BERT + koff);
                const ulonglong2* pb = (const ulonglong2*)(srcp + (size_t)rB * BERT + koff);
                #pragma unroll
                for (int j = 0; j < 6; j++) {
                    ulonglong2 va = pa[j]; xA[2*j] = va.x; xA[2*j+1] = va.y;
                    ulonglong2 vb = pb[j]; xB[2*j] = vb.x; xB[2*j+1] = vb.y;
                }
            }
            const float* Wb; const float* biasb; int wr0;
            if      (bb < 3)  { Wb = Wt2c;  biasb = bt2c;  wr0 = bb * 8; }
            else if (bb == 3) { Wb = Wcode; biasb = bcode; wr0 = 0; }
            else if (bb < 7)  { Wb = Wctx;  biasb = bctx;  wr0 = (bb - 4) * 8; }
            else              { Wb = Wctx;  biasb = bctx;  wr0 = (bb - 7) * 8; }

            float rA8[8], rB8[8];
            #pragma unroll
            for (int ob = 0; ob < 8; ob++) {
                const ulonglong2* w = (const ulonglong2*)(Wb + (size_t)(wr0 + ob) * BERT + koff);
                u64 sA = 0ull, sB = 0ull;
                #pragma unroll
                for (int j = 0; j < 6; j++) {
                    ulonglong2 wv = __ldg(w + j);
                    ffma2(sA, xA[2*j],   wv.x); ffma2(sA, xA[2*j+1], wv.y);
                    ffma2(sB, xB[2*j],   wv.x); ffma2(sB, xB[2*j+1], wv.y);
                }
                float a = hsum2(sA), b2v = hsum2(sB);
                a   += __shfl_xor_sync(0xffffffffu, a,   8);
                a   += __shfl_xor_sync(0xffffffffu, a,   16);
                b2v += __shfl_xor_sync(0xffffffffu, b2v, 8);
                b2v += __shfl_xor_sync(0xffffffffu, b2v, 16);
                rA8[ob] = a; rB8[ob] = b2v;
            }
            if (lane < 8) {
                float* p = sred + warp * 129 + rg * 16;
                #pragma unroll
                for (int ob = 0; ob < 8; ob++) { p[ob] = rA8[ob]; p[8 + ob] = rB8[ob]; }
            }
            __syncthreads();
            if (tid < 128) {
                int rr = tid >> 3, ob = tid & 7;
                float a = 0.f;
                #pragma unroll
                for (int w2 = 0; w2 < 8; w2++)
                    a += sred[w2 * 129 + (rr >> 1) * 16 + (rr & 1) * 8 + ob];
                if (row0 + rr < Bn)
                    g_proj[(row0 + rr) * 80 + bb * 8 + ob] = a + biasb[wr0 + ob];
            }
            __syncthreads();
        }
    } else if (bid < PB + nCtry) {
        // ---------- cet projection + norm (one country / block) ----------
        const int i = bid - PB;
        float* sv = sred;  // reuse shared
        const float* e = cemb + (size_t)i * BERT;
        #pragma unroll
        for (int t = 0; t < 3; t++) {
            int j = warp * 3 + t;
            const float* w = Wcet + (size_t)j * BERT;
            float a = 0.f;
            #pragma unroll
            for (int q = 0; q < 6; q++) {
                int k = lane * 4 + q * 128;
                float4 ev = *(const float4*)(e + k);
                float4 wv = *(const float4*)(w + k);
                a += ev.x * wv.x + ev.y * wv.y + ev.z * wv.z + ev.w * wv.w;
            }
            #pragma unroll
            for (int o = 16; o; o >>= 1) a += __shfl_xor_sync(0xffffffffu, a, o);
            if (lane == 0) sv[j] = a + bcet[j];
        }
        __syncthreads();
        if (tid < 32) {
            float v = (lane < CTRY) ? sv[lane] : 0.f;
            if (lane < CTRY) g_cet[i * CTRY + lane] = v;
            float s = v * v;
            #pragma unroll
            for (int o = 16; o; o >>= 1) s += __shfl_xor_sync(0xffffffffu, s, o);
            if (lane == 0) g_cetn[i] = sqrtf(s);
        }
    } else {
        // ---------- code-embedding norms ----------
        int i = (bid - PB - nCtry) * 256 + tid;
        if (i < nCodes) {
            float s = 0.f;
            #pragma unroll
            for (int j = 0; j < CODE; j++) { float v = codeTab[i * CODE + j]; s += v * v; }
            g_coden[i] = sqrtf(s);
        }
    }
}

// =====================================================================
// k_mlp: gathers + 4 cosines + MLP(13->24->24->1) + softmax over C=64
// block = 256 thr = 4 batch rows x 64 candidates
// =====================================================================
__global__ void __launch_bounds__(256, 4) k_mlp(
    const int* __restrict__ fcodes, const int* __restrict__ ccodes,
    const float* __restrict__ gaz,  const float* __restrict__ codeTab,
    const float* __restrict__ W1, const float* __restrict__ b1,
    const float* __restrict__ W2, const float* __restrict__ b2,
    const float* __restrict__ WL, const float* __restrict__ bL,
    float* __restrict__ out, int Bn)
{
    __shared__ __align__(16) float sW1T[NFEAT * MIX];   // [q][j] transposed
    __shared__ __align__(16) float sW2[MIX * MIX];      // [j][q]
    __shared__ __align__(16) float sB1[MIX];
    __shared__ float sB2[MIX], sWL[MIX];
    __shared__ __align__(16) float sGaz[4 * CMAX * GAZ];   // 2304
    __shared__ __align__(16) float sX[4 * 80];
    __shared__ float sN[4][4];
    __shared__ float sRed[4][2];
    __shared__ float sbL;

    const int tid = threadIdx.x;
    const int b0  = blockIdx.x * 4;

    for (int i = tid; i < NFEAT * MIX; i += 256) {
        int q = i / MIX, j = i % MIX;
        sW1T[i] = W1[j * NFEAT + q];
    }
    for (int i = tid; i < MIX * MIX; i += 256) sW2[i] = W2[i];
    if (tid < MIX) { sB1[tid] = b1[tid]; sB2[tid] = b2[tid]; sWL[tid] = WL[tid]; }
    if (tid == 0) sbL = bL[0];
    {   // coalesced gaz staging (float4)
        size_t g0 = (size_t)b0 * (CMAX * GAZ / 4) * 1;      // b0*576 float4
        int cnt = min(576, (Bn - b0) * 144);
        const float4* gp = (const float4*)gaz + (size_t)b0 * 144;
        float4* sp = (float4*)sGaz;
        for (int i = tid; i < cnt; i += 256) sp[i] = __ldg(gp + i);
        (void)g0;
    }
    for (int i = tid; i < 4 * 80; i += 256) {
        int bb = min(b0 + i / 80, Bn - 1);
        sX[i] = g_proj[bb * 80 + (i % 80)];
    }
    __syncthreads();

    if (tid < 16) {
        int gg = tid >> 2, which = tid & 3;
        int off = (which == 0) ? 0 : (which == 1) ? 24 : (which == 2) ? 32 : 56;
        int cnt = (which == 1) ? CODE : CTRY;
        float ss = 0.f;
        for (int j = 0; j < cnt; j++) { float v = sX[gg * 80 + off + j]; ss += v * v; }
        sN[gg][which] = fmaxf(sqrtf(ss), 1e-8f);
    }
    __syncthreads();

    const int g = tid >> 6;
    const int c = tid & 63;
    const int b = min(b0 + g, Bn - 1);
    const int idx = b * CMAX + c;
    const int fc = fcodes[idx], cc = ccodes[idx];
    const float* sx = sX + g * 80;

    // cosine dots, packed f32x2, vectorized gathers
    const ulonglong2* cet2 = (const ulonglong2*)(g_cet + cc * CTRY);
    const u64* x1 = (const u64*)(sx);
    const u64* x3 = (const u64*)(sx + 32);
    const u64* x4 = (const u64*)(sx + 56);
    u64 d1 = 0ull, d3 = 0ull, d4 = 0ull;
    #pragma unroll
    for (int j = 0; j < 6; j++) {
        ulonglong2 cv = __ldg(cet2 + j);
        ffma2(d1, x1[2*j], cv.x); ffma2(d1, x1[2*j+1], cv.y);
        ffma2(d3, x3[2*j], cv.x); ffma2(d3, x3[2*j+1], cv.y);
        ffma2(d4, x4[2*j], cv.x); ffma2(d4, x4[2*j+1], cv.y);
    }
    const ulonglong2* fe2 = (const ulonglong2*)(codeTab + fc * CODE);
    const u64* x2p = (const u64*)(sx + 24);
    u64 d2 = 0ull;
    #pragma unroll
    for (int j = 0; j < 2; j++) {
        ulonglong2 cv = __ldg(fe2 + j);
        ffma2(d2, x2p[2*j], cv.x); ffma2(d2, x2p[2*j+1], cv.y);
    }
    float nb = fmaxf(g_cetn[cc], 1e-8f);
    float f0 = hsum2(d1) / (sN[g][0] * nb);
    float f1 = hsum2(d2) / (sN[g][1] * fmaxf(g_coden[fc], 1e-8f));
    float f2 = hsum2(d3) / (sN[g][2] * nb);
    float f3 = hsum2(d4) / (sN[g][3] * nb);

    // ---- layer 1: feature-outer, packed accumulators over output pairs ----
    u64 acc2[12];
    const u64* b1p = (const u64*)sB1;
    #pragma unroll
    for (int j = 0; j < 12; j++) acc2[j] = b1p[j];

    const float* gz = sGaz + (g * CMAX + c) * GAZ;
    #pragma unroll
    for (int q = 0; q < NFEAT; q++) {
        float f = (q == 0) ? f0 : (q == 1) ? f1 : (q == 2) ? f2 : (q == 3) ? f3
                : gz[q - 4];
        u64 ff = pack2(f, f);
        const ulonglong2* wc = (const ulonglong2*)(sW1T + q * MIX);
        #pragma unroll
        for (int j2 = 0; j2 < 6; j2++) {
            ulonglong2 wv = wc[j2];
            ffma2(acc2[2*j2],   ff, wv.x);
            ffma2(acc2[2*j2+1], ff, wv.y);
        }
    }
    u64 h1p[12];
    #pragma unroll
    for (int j = 0; j < 12; j++) {
        float lo, hi; unpack2(acc2[j], lo, hi);
        h1p[j] = pack2(sigf(lo), sigf(hi));
    }

    // ---- layer 2 + last fused ----
    float last = sbL;
    #pragma unroll
    for (int j = 0; j < MIX; j++) {
        const ulonglong2* wr = (const ulonglong2*)(sW2 + j * MIX);
        u64 a2 = 0ull;
        #pragma unroll
        for (int q2 = 0; q2 < 6; q2++) {
            ulonglong2 wv = wr[q2];
            ffma2(a2, h1p[2*q2],   wv.x);
            ffma2(a2, h1p[2*q2+1], wv.y);
        }
        float a = sB2[j] + hsum2(a2);
        last = fmaf(sWL[j], sigf(a), last);
    }

    // ---- softmax over 64 candidates (2 warps / group) ----
    float m = last;
    #pragma unroll
    for (int o = 16; o; o >>= 1) m = fmaxf(m, __shfl_xor_sync(0xffffffffu, m, o));
    int wh = (tid >> 5) & 1;
    if ((tid & 31) == 0) sRed[g][wh] = m;
    __syncthreads();
    m = fmaxf(sRed[g][0], sRed[g][1]);
    float e = __expf(last - m);
    float ss = e;
    #pragma unroll
    for (int o = 16; o; o >>= 1) ss += __shfl_xor_sync(0xffffffffu, ss, o);
    __syncthreads();
    if ((tid & 31) == 0) sRed[g][wh] = ss;
    __syncthreads();
    ss = sRed[g][0] + sRed[g][1];
    if (b0 + g < Bn) out[idx] = e / ss;
}

// =====================================================================
extern "C" void kernel_launch(void* const* d_in, const int* in_sizes, int n_in,
                              void* d_out, int out_size)
{
    const float* place  = (const float*)d_in[0];
    const float* other  = (const float*)d_in[1];
    const float* doc    = (const float*)d_in[2];
    const int*   fcodes = (const int*)  d_in[3];
    const int*   ccodes = (const int*)  d_in[4];
    const float* gaz    = (const float*)d_in[5];
    const float* codeTab= (const float*)d_in[6];
    const float* ctryTab= (const float*)d_in[7];
    const float* Wcet   = (const float*)d_in[8];
    const float* bcet   = (const float*)d_in[9];
    const float* Wt2c   = (const float*)d_in[10];
    const float* bt2c   = (const float*)d_in[11];
    const float* Wctx   = (const float*)d_in[12];
    const float* bctx   = (const float*)d_in[13];
    const float* Wcode  = (const float*)d_in[14];
    const float* bcode  = (const float*)d_in[15];
    const float* W1     = (const float*)d_in[16];
    const float* b1     = (const float*)d_in[17];
    const float* W2     = (const float*)d_in[18];
    const float* b2     = (const float*)d_in[19];
    const float* WL     = (const float*)d_in[20];
    const float* bL     = (const float*)d_in[21];
    float* out = (float*)d_out;

    int B      = in_sizes[0] / BERT;
    int nCtry  = in_sizes[7] / BERT;
    int nCodes = in_sizes[6] / CODE;

    int PB = (B + 15) / 16;
    int grid = PB + nCtry + (nCodes + 255) / 256;

    k_pre<<<grid, 256>>>(place, other, doc,
                         Wt2c, bt2c, Wcode, bcode, Wctx, bctx,
                         ctryTab, Wcet, bcet, codeTab,
                         PB, nCtry, nCodes, B);
    k_mlp<<<(B + 3) / 4, 256>>>(fcodes, ccodes, gaz, codeTab,
                                W1, b1, W2, b2, WL, bL, out, B);
}

// round 7
// speedup vs baseline: 1.7461x; 1.4043x over previous
#include <cuda_runtime.h>
#include <math.h>

typedef unsigned long long u64;

// ---------------- shapes ----------------
#define BERT 768
#define CTRY 24
#define CODE 8
#define GAZ  9
#define MIX  24
#define NFEAT 13
#define CMAX 64
#define B_MAX 2048
#define NCTRY_MAX 512
#define NCODES_MAX 1024

// ---------------- device scratch ----------------
__device__ float g_cet [NCTRY_MAX * CTRY];
__device__ float g_cetn[NCTRY_MAX];
__device__ float g_coden[NCODES_MAX];
__device__ float g_proj[B_MAX * 80];   // x(24) | x_code(8) | x_other(24) | x_doc(24)

// ---------------- f32x2 helpers ----------------
__device__ __forceinline__ void ffma2(u64& d, u64 a, u64 b) {
    asm("fma.rn.f32x2 %0, %1, %2, %0;" : "+l"(d) : "l"(a), "l"(b));
}
__device__ __forceinline__ u64 pack2(float lo, float hi) {
    u64 r; asm("mov.b64 %0, {%1,%2};" : "=l"(r) : "f"(lo), "f"(hi)); return r;
}
__device__ __forceinline__ void unpack2(u64 v, float& lo, float& hi) {
    asm("mov.b64 {%0,%1}, %2;" : "=f"(lo), "=f"(hi) : "l"(v));
}
__device__ __forceinline__ float hsum2(u64 v) {
    float lo, hi; unpack2(v, lo, hi); return lo + hi;
}
__device__ __forceinline__ float sigf(float x) {
    float t; asm("tanh.approx.f32 %0, %1;" : "=f"(t) : "f"(x * 0.5f));
    return fmaf(0.5f, t, 0.5f);
}

// =====================================================================
// Fused pre-kernel: [0,PB) proj | [PB,PB+CB) cet (4/block) | rest coden
// proj: 16 rows/block, 2 rows/thread, 32 k-slices of 24; weights staged
// through double-buffered SMEM (LDS instead of L2-latency LDG).
// =====================================================================
__global__ void __launch_bounds__(256, 2) k_pre(
    const float* __restrict__ place, const float* __restrict__ other,
    const float* __restrict__ doc,
    const float* __restrict__ Wt2c, const float* __restrict__ bt2c,
    const float* __restrict__ Wcode, const float* __restrict__ bcode,
    const float* __restrict__ Wctx, const float* __restrict__ bctx,
    const float* __restrict__ cemb, const float* __restrict__ Wcet,
    const float* __restrict__ bcet, const float* __restrict__ codeTab,
    int PB, int CB, int nCtry, int nCodes, int Bn)
{
    __shared__ __align__(16) float sW[2][8 * BERT];   // 48KB double buffer
    __shared__ float sred[8 * 129 + 8];
    const int bid  = blockIdx.x;
    const int tid  = threadIdx.x;
    const int warp = tid >> 5, lane = tid & 31;

    if (bid < PB) {
        const int rg   = lane & 7;
        const int ks   = (warp << 2) | (lane >> 3);
        const int koff = ks * 24;
        const int row0 = bid * 16;
        const int rA = min(row0 + rg * 2,     Bn - 1);
        const int rB = min(row0 + rg * 2 + 1, Bn - 1);

        u64 xA[12], xB[12];
        float4 wst[6];

        // prologue: stage W for bb=0 (Wt2c rows 0..7)
        {
            const float4* src = (const float4*)Wt2c;
            #pragma unroll
            for (int j = 0; j < 6; j++) wst[j] = __ldg(src + tid + j * 256);
            float4* dst = (float4*)sW[0];
            #pragma unroll
            for (int j = 0; j < 6; j++) dst[tid + j * 256] = wst[j];
        }
        __syncthreads();

        int cur = 0;
        #pragma unroll 1
        for (int bb = 0; bb < 10; bb++) {
            // prefetch next pass's weights into registers
            if (bb < 9) {
                int nb = bb + 1;
                const float* Wn;
                if      (nb < 3)  Wn = Wt2c  + nb * 8 * BERT;
                else if (nb == 3) Wn = Wcode;
                else if (nb < 7)  Wn = Wctx  + (nb - 4) * 8 * BERT;
                else              Wn = Wctx  + (nb - 7) * 8 * BERT;
                const float4* src = (const float4*)Wn;
                #pragma unroll
                for (int j = 0; j < 6; j++) wst[j] = __ldg(src + tid + j * 256);
            }
            // (re)load x on source switch
            if (bb == 0 || bb == 4 || bb == 7) {
                const float* srcp = (bb == 0) ? place : (bb == 4) ? other : doc;
                const ulonglong2* pa = (const ulonglong2*)(srcp + (size_t)rA * BERT + koff);
                const ulonglong2* pb = (const ulonglong2*)(srcp + (size_t)rB * BERT + koff);
                #pragma unroll
                for (int j = 0; j < 6; j++) {
                    ulonglong2 va = __ldg(pa + j); xA[2*j] = va.x; xA[2*j+1] = va.y;
                    ulonglong2 vb = __ldg(pb + j); xB[2*j] = vb.x; xB[2*j+1] = vb.y;
                }
            }
            const float* biasb; int wr0;
            if      (bb < 3)  { biasb = bt2c;  wr0 = bb * 8; }
            else if (bb == 3) { biasb = bcode; wr0 = 0; }
            else if (bb < 7)  { biasb = bctx;  wr0 = (bb - 4) * 8; }
            else              { biasb = bctx;  wr0 = (bb - 7) * 8; }

            const float* Wsm = sW[cur];
            float rA8[8], rB8[8];
            #pragma unroll
            for (int ob = 0; ob < 8; ob++) {
                const ulonglong2* w = (const ulonglong2*)(Wsm + ob * BERT + koff);
                u64 sA = 0ull, sB = 0ull;
                #pragma unroll
                for (int j = 0; j < 6; j++) {
                    ulonglong2 wv = w[j];
                    ffma2(sA, xA[2*j],   wv.x); ffma2(sA, xA[2*j+1], wv.y);
                    ffma2(sB, xB[2*j],   wv.x); ffma2(sB, xB[2*j+1], wv.y);
                }
                float a = hsum2(sA), bv = hsum2(sB);
                a  += __shfl_xor_sync(0xffffffffu, a,  8);
                a  += __shfl_xor_sync(0xffffffffu, a,  16);
                bv += __shfl_xor_sync(0xffffffffu, bv, 8);
                bv += __shfl_xor_sync(0xffffffffu, bv, 16);
                rA8[ob] = a; rB8[ob] = bv;
            }
            if (lane < 8) {
                float* p = sred + warp * 129 + rg * 16;
                #pragma unroll
                for (int ob = 0; ob < 8; ob++) { p[ob] = rA8[ob]; p[8 + ob] = rB8[ob]; }
            }
            __syncthreads();
            // store prefetched W into the other buffer
            if (bb < 9) {
                float4* dst = (float4*)sW[cur ^ 1];
                #pragma unroll
                for (int j = 0; j < 6; j++) dst[tid + j * 256] = wst[j];
            }
            if (tid < 128) {
                int rr = tid >> 3, ob = tid & 7;
                float a = 0.f;
                #pragma unroll
                for (int w2 = 0; w2 < 8; w2++)
                    a += sred[w2 * 129 + (rr >> 1) * 16 + (rr & 1) * 8 + ob];
                if (row0 + rr < Bn)
                    g_proj[(row0 + rr) * 80 + bb * 8 + ob] = a + biasb[wr0 + ob];
            }
            __syncthreads();
            cur ^= 1;
        }
    } else if (bid < PB + CB) {
        // ---------- cet projection + norm, 4 countries / block ----------
        float* sv = sred;
        const int i0 = (bid - PB) * 4;
        #pragma unroll 1
        for (int t4 = 0; t4 < 4; t4++) {
            int i = i0 + t4;
            if (i < nCtry) {
                const float* e = cemb + (size_t)i * BERT;
                #pragma unroll
                for (int t = 0; t < 3; t++) {
                    int j = warp * 3 + t;
                    const float* w = Wcet + (size_t)j * BERT;
                    float a = 0.f;
                    #pragma unroll
                    for (int q = 0; q < 6; q++) {
                        int k = lane * 4 + q * 128;
                        float4 ev = *(const float4*)(e + k);
                        float4 wv = __ldg((const float4*)(w + k));
                        a += ev.x * wv.x + ev.y * wv.y + ev.z * wv.z + ev.w * wv.w;
                    }
                    #pragma unroll
                    for (int o = 16; o; o >>= 1) a += __shfl_xor_sync(0xffffffffu, a, o);
                    if (lane == 0) sv[j] = a + bcet[j];
                }
            }
            __syncthreads();
            if (i < nCtry && tid < 32) {
                float v = (lane < CTRY) ? sv[lane] : 0.f;
                if (lane < CTRY) g_cet[i * CTRY + lane] = v;
                float s = v * v;
                #pragma unroll
                for (int o = 16; o; o >>= 1) s += __shfl_xor_sync(0xffffffffu, s, o);
                if (lane == 0) g_cetn[i] = sqrtf(s);
            }
            __syncthreads();
        }
    } else {
        int i = (bid - PB - CB) * 256 + tid;
        if (i < nCodes) {
            float s = 0.f;
            #pragma unroll
            for (int j = 0; j < CODE; j++) { float v = codeTab[i * CODE + j]; s += v * v; }
            g_coden[i] = sqrtf(s);
        }
    }
}

// =====================================================================
// k_mlp: 128 threads = 4 rows x 32 lanes; each lane does candidates
// c=lane and c=lane+32 -> every weight LDS feeds 4 FFMA2; softmax is a
// pure warp reduction.
// =====================================================================
__global__ void __launch_bounds__(128, 5) k_mlp(
    const int* __restrict__ fcodes, const int* __restrict__ ccodes,
    const float* __restrict__ gaz,  const float* __restrict__ codeTab,
    const float* __restrict__ W1, const float* __restrict__ b1,
    const float* __restrict__ W2, const float* __restrict__ b2,
    const float* __restrict__ WL, const float* __restrict__ bL,
    float* __restrict__ out, int Bn)
{
    __shared__ __align__(16) float sW1T[NFEAT * MIX];   // [q][j]
    __shared__ __align__(16) float sW2[MIX * MIX];      // [j][q]
    __shared__ __align__(16) float sB1[MIX];
    __shared__ float sB2[MIX], sWL[MIX];
    __shared__ __align__(16) float sGaz[4 * CMAX * GAZ];
    __shared__ __align__(16) float sX[4 * 80];
    __shared__ float sN[4][4];
    __shared__ float sbL;

    const int tid = threadIdx.x;
    const int b0  = blockIdx.x * 4;

    for (int i = tid; i < NFEAT * MIX; i += 128) {
        int q = i / MIX, j = i - q * MIX;
        sW1T[i] = W1[j * NFEAT + q];
    }
    for (int i = tid; i < MIX * MIX; i += 128) sW2[i] = W2[i];
    if (tid < MIX) { sB1[tid] = b1[tid]; sB2[tid] = b2[tid]; sWL[tid] = WL[tid]; }
    if (tid == 0) sbL = bL[0];
    {
        int cnt = min(576, (Bn - b0) * 144);
        const float4* gp = (const float4*)gaz + (size_t)b0 * 144;
        float4* sp = (float4*)sGaz;
        for (int i = tid; i < cnt; i += 128) sp[i] = __ldg(gp + i);
    }
    for (int i = tid; i < 4 * 80; i += 128) {
        int bb = min(b0 + i / 80, Bn - 1);
        sX[i] = g_proj[bb * 80 + (i % 80)];
    }
    __syncthreads();

    if (tid < 16) {
        int gg = tid >> 2, which = tid & 3;
        int off = (which == 0) ? 0 : (which == 1) ? 24 : (which == 2) ? 32 : 56;
        int cnt = (which == 1) ? CODE : CTRY;
        float ss = 0.f;
        for (int j = 0; j < cnt; j++) { float v = sX[gg * 80 + off + j]; ss += v * v; }
        sN[gg][which] = fmaxf(sqrtf(ss), 1e-8f);
    }
    __syncthreads();

    const int g    = tid >> 5;
    const int lane = tid & 31;
    const int b    = min(b0 + g, Bn - 1);
    const int idx0 = b * CMAX + lane;
    const int idx1 = idx0 + 32;
    const int fc0 = fcodes[idx0], cc0 = ccodes[idx0];
    const int fc1 = fcodes[idx1], cc1 = ccodes[idx1];
    const float* sx = sX + g * 80;

    // ---- cosine dots for both candidates ----
    const ulonglong2* cet0 = (const ulonglong2*)(g_cet + cc0 * CTRY);
    const ulonglong2* cet1 = (const ulonglong2*)(g_cet + cc1 * CTRY);
    const u64* x1 = (const u64*)(sx);
    const u64* x3 = (const u64*)(sx + 32);
    const u64* x4 = (const u64*)(sx + 56);
    u64 p10=0, p30=0, p40=0, p11=0, p31=0, p41=0;
    #pragma unroll
    for (int j = 0; j < 6; j++) {
        ulonglong2 c0 = __ldg(cet0 + j);
        ulonglong2 c1 = __ldg(cet1 + j);
        u64 xa = x1[2*j], xb = x1[2*j+1];
        ffma2(p10, xa, c0.x); ffma2(p10, xb, c0.y);
        ffma2(p11, xa, c1.x); ffma2(p11, xb, c1.y);
        xa = x3[2*j]; xb = x3[2*j+1];
        ffma2(p30, xa, c0.x); ffma2(p30, xb, c0.y);
        ffma2(p31, xa, c1.x); ffma2(p31, xb, c1.y);
        xa = x4[2*j]; xb = x4[2*j+1];
        ffma2(p40, xa, c0.x); ffma2(p40, xb, c0.y);
        ffma2(p41, xa, c1.x); ffma2(p41, xb, c1.y);
    }
    const ulonglong2* fe0 = (const ulonglong2*)(codeTab + fc0 * CODE);
    const ulonglong2* fe1 = (const ulonglong2*)(codeTab + fc1 * CODE);
    const u64* x2p = (const u64*)(sx + 24);
    u64 p20 = 0, p21 = 0;
    #pragma unroll
    for (int j = 0; j < 2; j++) {
        ulonglong2 c0 = __ldg(fe0 + j);
        ulonglong2 c1 = __ldg(fe1 + j);
        u64 xa = x2p[2*j], xb = x2p[2*j+1];
        ffma2(p20, xa, c0.x); ffma2(p20, xb, c0.y);
        ffma2(p21, xa, c1.x); ffma2(p21, xb, c1.y);
    }
    float nb0 = fmaxf(g_cetn[cc0], 1e-8f);
    float nb1 = fmaxf(g_cetn[cc1], 1e-8f);
    float feat0[4], feat1[4];
    feat0[0] = __fdividef(hsum2(p10), sN[g][0] * nb0);
    feat0[1] = __fdividef(hsum2(p20), sN[g][1] * fmaxf(g_coden[fc0], 1e-8f));
    feat0[2] = __fdividef(hsum2(p30), sN[g][2] * nb0);
    feat0[3] = __fdividef(hsum2(p40), sN[g][3] * nb0);
    feat1[0] = __fdividef(hsum2(p11), sN[g][0] * nb1);
    feat1[1] = __fdividef(hsum2(p21), sN[g][1] * fmaxf(g_coden[fc1], 1e-8f));
    feat1[2] = __fdividef(hsum2(p31), sN[g][2] * nb1);
    feat1[3] = __fdividef(hsum2(p41), sN[g][3] * nb1);

    // ---- layer 1 (feature-outer), both candidates share weight loads ----
    u64 a0[12], a1[12];
    const u64* b1p = (const u64*)sB1;
    #pragma unroll
    for (int j = 0; j < 12; j++) { a0[j] = b1p[j]; a1[j] = b1p[j]; }

    const float* gz0 = sGaz + ((g * CMAX) + lane) * GAZ;
    const float* gz1 = gz0 + 32 * GAZ;
    #pragma unroll
    for (int q = 0; q < NFEAT; q++) {
        float f0 = (q < 4) ? feat0[q] : gz0[q - 4];
        float f1 = (q < 4) ? feat1[q] : gz1[q - 4];
        u64 ff0 = pack2(f0, f0), ff1 = pack2(f1, f1);
        const ulonglong2* wc = (const ulonglong2*)(sW1T + q * MIX);
        #pragma unroll
        for (int j2 = 0; j2 < 6; j2++) {
            ulonglong2 wv = wc[j2];
            ffma2(a0[2*j2],   ff0, wv.x); ffma2(a0[2*j2+1], ff0, wv.y);
            ffma2(a1[2*j2],   ff1, wv.x); ffma2(a1[2*j2+1], ff1, wv.y);
        }
    }
    #pragma unroll
    for (int j = 0; j < 12; j++) {
        float lo, hi;
        unpack2(a0[j], lo, hi); a0[j] = pack2(sigf(lo), sigf(hi));
        unpack2(a1[j], lo, hi); a1[j] = pack2(sigf(lo), sigf(hi));
    }

    // ---- layer 2 + last, both candidates share weight loads ----
    float last0 = sbL, last1 = sbL;
    #pragma unroll
    for (int j = 0; j < MIX; j++) {
        const ulonglong2* wr = (const ulonglong2*)(sW2 + j * MIX);
        u64 s0 = 0ull, s1 = 0ull;
        #pragma unroll
        for (int q2 = 0; q2 < 6; q2++) {
            ulonglong2 wv = wr[q2];
            ffma2(s0, a0[2*q2],   wv.x); ffma2(s0, a0[2*q2+1], wv.y);
            ffma2(s1, a1[2*q2],   wv.x); ffma2(s1, a1[2*q2+1], wv.y);
        }
        float v0 = sB2[j] + hsum2(s0);
        float v1 = sB2[j] + hsum2(s1);
        last0 = fmaf(sWL[j], sigf(v0), last0);
        last1 = fmaf(sWL[j], sigf(v1), last1);
    }

    // ---- warp softmax over 64 candidates ----
    float m = fmaxf(last0, last1);
    #pragma unroll
    for (int o = 16; o; o >>= 1) m = fmaxf(m, __shfl_xor_sync(0xffffffffu, m, o));
    float e0 = __expf(last0 - m);
    float e1 = __expf(last1 - m);
    float ss = e0 + e1;
    #pragma unroll
    for (int o = 16; o; o >>= 1) ss += __shfl_xor_sync(0xffffffffu, ss, o);
    float inv = __fdividef(1.f, ss);
    if (b0 + g < Bn) {
        out[idx0] = e0 * inv;
        out[idx1] = e1 * inv;
    }
}

// =====================================================================
extern "C" void kernel_launch(void* const* d_in, const int* in_sizes, int n_in,
                              void* d_out, int out_size)
{
    const float* place  = (const float*)d_in[0];
    const float* other  = (const float*)d_in[1];
    const float* doc    = (const float*)d_in[2];
    const int*   fcodes = (const int*)  d_in[3];
    const int*   ccodes = (const int*)  d_in[4];
    const float* gaz    = (const float*)d_in[5];
    const float* codeTab= (const float*)d_in[6];
    const float* ctryTab= (const float*)d_in[7];
    const float* Wcet   = (const float*)d_in[8];
    const float* bcet   = (const float*)d_in[9];
    const float* Wt2c   = (const float*)d_in[10];
    const float* bt2c   = (const float*)d_in[11];
    const float* Wctx   = (const float*)d_in[12];
    const float* bctx   = (const float*)d_in[13];
    const float* Wcode  = (const float*)d_in[14];
    const float* bcode  = (const float*)d_in[15];
    const float* W1     = (const float*)d_in[16];
    const float* b1     = (const float*)d_in[17];
    const float* W2     = (const float*)d_in[18];
    const float* b2     = (const float*)d_in[19];
    const float* WL     = (const float*)d_in[20];
    const float* bL     = (const float*)d_in[21];
    float* out = (float*)d_out;

    int B      = in_sizes[0] / BERT;
    int nCtry  = in_sizes[7] / BERT;
    int nCodes = in_sizes[6] / CODE;

    int PB = (B + 15) / 16;
    int CB = (nCtry + 3) / 4;
    int grid = PB + CB + (nCodes + 255) / 256;

    k_pre<<<grid, 256>>>(place, other, doc,
                         Wt2c, bt2c, Wcode, bcode, Wctx, bctx,
                         ctryTab, Wcet, bcet, codeTab,
                         PB, CB, nCtry, nCodes, B);
    k_mlp<<<(B + 3) / 4, 128>>>(fcodes, ccodes, gaz, codeTab,
                                W1, b1, W2, b2, WL, bL, out, B);
}